// round 13
// baseline (speedup 1.0000x reference)
#include <cuda_runtime.h>
#include <cuda_fp16.h>
#include <cfloat>
#include <cmath>
#include <cstdint>

// Problem constants
constexpr int B_ = 2;
constexpr int S_ = 2048;
constexpr int E_ = 2048;
constexpr int H_ = 16;
constexpr int D_ = 128;
constexpr int M_ = B_ * S_;   // 4096 rows for all GEMMs

// Scratch (static device globals: allowed; no dynamic allocation)
__device__ float g_Q[(size_t)B_ * S_ * E_];
__device__ float g_K[(size_t)B_ * S_ * E_];
__device__ float g_V[(size_t)B_ * S_ * E_];
__device__ __align__(256) __half g_ctx[(size_t)B_ * S_ * E_];   // fp16 ctx
// prepared GEMM inputs (fp16): x row-major [m][k]; weights transposed [n][k]
__device__ __align__(256) __half g_Xh [(size_t)M_ * E_];
__device__ __align__(256) __half g_WqT[(size_t)E_ * E_];
__device__ __align__(256) __half g_WkT[(size_t)E_ * E_];
__device__ __align__(256) __half g_WvT[(size_t)E_ * E_];
__device__ __align__(256) __half g_WoT[(size_t)E_ * E_];

// ---------------------------------------------------------------------------
// helpers
// ---------------------------------------------------------------------------
__device__ __forceinline__ uint32_t smem_u32(const void* p) {
    uint32_t a;
    asm("{ .reg .u64 t; cvta.to.shared.u64 t, %1; cvt.u32.u64 %0, t; }"
        : "=r"(a) : "l"(p));
    return a;
}
__device__ __forceinline__ void cp_async16(uint32_t dst, const void* src) {
    asm volatile("cp.async.cg.shared.global [%0], [%1], 16;\n"
                 :: "r"(dst), "l"(src));
}
__device__ __forceinline__ void cp_commit() {
    asm volatile("cp.async.commit_group;\n");
}
template <int N>
__device__ __forceinline__ void cp_wait() {
    asm volatile("cp.async.wait_group %0;\n" :: "n"(N));
}

// fp16 MMA, fp32 accumulate: D(16x8) += A(16x16) * B(16x8)
__device__ __forceinline__ void mma_fp16(
    float* c, uint32_t a0, uint32_t a1, uint32_t a2, uint32_t a3,
    uint32_t b0, uint32_t b1)
{
    asm volatile(
        "mma.sync.aligned.m16n8k16.row.col.f32.f16.f16.f32 "
        "{%0,%1,%2,%3}, {%4,%5,%6,%7}, {%8,%9}, {%0,%1,%2,%3};\n"
        : "+f"(c[0]), "+f"(c[1]), "+f"(c[2]), "+f"(c[3])
        : "r"(a0), "r"(a1), "r"(a2), "r"(a3), "r"(b0), "r"(b1));
}

// ---------------------------------------------------------------------------
// Pre-pass: x -> fp16; weights -> transposed [n][k] fp16
// ---------------------------------------------------------------------------
__global__ void __launch_bounds__(256) cvt_x_kernel(const float* __restrict__ x)
{
    const size_t n4 = (size_t)M_ * E_ / 4;
    const size_t stride = (size_t)gridDim.x * blockDim.x;
    for (size_t i = (size_t)blockIdx.x * blockDim.x + threadIdx.x; i < n4;
         i += stride) {
        float4 v = ((const float4*)x)[i];
        __half2 h0 = __floats2half2_rn(v.x, v.y);
        __half2 h1 = __floats2half2_rn(v.z, v.w);
        uint2 o;
        o.x = *(uint32_t*)&h0;
        o.y = *(uint32_t*)&h1;
        ((uint2*)g_Xh)[i] = o;
    }
}

__global__ void __launch_bounds__(256) transpose_w_kernel(
    const float* __restrict__ wq, const float* __restrict__ wk,
    const float* __restrict__ wv, const float* __restrict__ wo)
{
    const float* src; __half* dst;
    switch (blockIdx.z) {
        case 0: src = wq; dst = g_WqT; break;
        case 1: src = wk; dst = g_WkT; break;
        case 2: src = wv; dst = g_WvT; break;
        default: src = wo; dst = g_WoT; break;
    }
    __shared__ float t[32][33];
    const int tx = threadIdx.x, ty = threadIdx.y;
    const int bx = blockIdx.x * 32, by = blockIdx.y * 32;
#pragma unroll
    for (int i = 0; i < 4; i++)
        t[ty + i * 8][tx] = src[(size_t)(by + ty + i * 8) * E_ + bx + tx];
    __syncthreads();
#pragma unroll
    for (int i = 0; i < 4; i++)
        dst[(size_t)(bx + ty + i * 8) * E_ + by + tx] =
            __float2half_rn(t[tx][ty + i * 8]);
}

// ---------------------------------------------------------------------------
// fp16 tensor-core GEMM: C[M,N] = A[M,K] @ Wt^T  (Wt is [N,K] fp16 K-major)
// CTA tile 128x256, 8 warps (wm 0..1 x wn 0..3), warp tile 64x64
// (mt 4 x nt 8 of m16n8k16). BK=32. 3-stage cp.async pipeline.
// A smem [128][40] halves (h2 stride 20: conflict-free frags);
// B smem [256][40] halves.
// ---------------------------------------------------------------------------
constexpr int NT_K      = E_ / 32;            // 64 k-tiles
constexpr int AROW_H    = 40;                 // halves per smem row (80B)
constexpr int A_STAGE_B = 128 * AROW_H * 2;   // 10240
constexpr int B_STAGE_B = 256 * AROW_H * 2;   // 20480
constexpr int STAGE_B   = A_STAGE_B + B_STAGE_B;   // 30720
constexpr int NSTG      = 3;
constexpr int GEMM_SMEM_BYTES = NSTG * STAGE_B;    // 92160

__device__ __forceinline__ void gemm_fp16_128x256(
    const __half* __restrict__ A, const __half* __restrict__ Wt,
    float* __restrict__ C, const float* __restrict__ bias)
{
    constexpr int K = E_;
    constexpr int N = E_;
    extern __shared__ char sm8[];
    const uint32_t sb = smem_u32(sm8);

    const int tid  = threadIdx.x;
    const int lane = tid & 31;
    const int warp = tid >> 5;
    const int quad = lane >> 2;
    const int tq   = lane & 3;
    const int wm   = warp >> 2;           // 0..1
    const int wn   = warp & 3;            // 0..3
    const int bm0  = blockIdx.y * 128;
    const int bn0  = blockIdx.x * 256;

    float acc[4][8][4];
#pragma unroll
    for (int mt = 0; mt < 4; mt++)
#pragma unroll
        for (int nt = 0; nt < 8; nt++)
#pragma unroll
            for (int r = 0; r < 4; r++) acc[mt][nt][r] = 0.f;

    auto load_tile = [&](int t) {
        const uint32_t so = sb + (uint32_t)((t % NSTG) * STAGE_B);
        const __half* Ag = A  + (size_t)bm0 * K + t * 32;
        const __half* Bg = Wt + (size_t)bn0 * K + t * 32;
#pragma unroll
        for (int i = 0; i < 2; i++) {                 // A: 512 chunks
            int idx = tid + i * 256;
            int r = idx >> 2, c = idx & 3;
            cp_async16(so + r * 80 + c * 16, Ag + (size_t)r * K + c * 8);
        }
#pragma unroll
        for (int i = 0; i < 4; i++) {                 // B: 1024 chunks
            int idx = tid + i * 256;
            int r = idx >> 2, c = idx & 3;
            cp_async16(so + A_STAGE_B + r * 80 + c * 16,
                       Bg + (size_t)r * K + c * 8);
        }
        cp_commit();
    };

    load_tile(0);
    load_tile(1);

    for (int t = 0; t < NT_K; t++) {
        if (t + 1 < NT_K) cp_wait<1>(); else cp_wait<0>();
        __syncthreads();
        if (t + 2 < NT_K) load_tile(t + 2);

        const uint32_t* Ah =
            (const uint32_t*)(sm8 + (t % NSTG) * STAGE_B);
        const uint32_t* Bh =
            (const uint32_t*)(sm8 + (t % NSTG) * STAGE_B + A_STAGE_B);

#pragma unroll
        for (int kc = 0; kc < 2; kc++) {               // two k16 chunks
            const int k0 = kc * 8;                     // h2 units
            uint32_t a[4][4], b[8][2];
#pragma unroll
            for (int mt = 0; mt < 4; mt++) {
                const int mb = wm * 64 + mt * 16;
                a[mt][0] = Ah[(mb + quad)     * 20 + k0 + tq];
                a[mt][1] = Ah[(mb + 8 + quad) * 20 + k0 + tq];
                a[mt][2] = Ah[(mb + quad)     * 20 + k0 + 4 + tq];
                a[mt][3] = Ah[(mb + 8 + quad) * 20 + k0 + 4 + tq];
            }
#pragma unroll
            for (int nt = 0; nt < 8; nt++) {
                const int nb = wn * 64 + nt * 8;
                b[nt][0] = Bh[(nb + quad) * 20 + k0 + tq];
                b[nt][1] = Bh[(nb + quad) * 20 + k0 + 4 + tq];
            }
#pragma unroll
            for (int mt = 0; mt < 4; mt++)
#pragma unroll
                for (int nt = 0; nt < 8; nt++)
                    mma_fp16(acc[mt][nt],
                             a[mt][0], a[mt][1], a[mt][2], a[mt][3],
                             b[nt][0], b[nt][1]);
        }
    }

    // Epilogue
#pragma unroll
    for (int mt = 0; mt < 4; mt++) {
        const int row = bm0 + wm * 64 + mt * 16 + quad;
#pragma unroll
        for (int nt = 0; nt < 8; nt++) {
            const int col = bn0 + wn * 64 + nt * 8 + 2 * tq;
            float bv0 = bias ? bias[col]     : 0.f;
            float bv1 = bias ? bias[col + 1] : 0.f;
            float2 r0, r1;
            r0.x = acc[mt][nt][0] + bv0; r0.y = acc[mt][nt][1] + bv1;
            r1.x = acc[mt][nt][2] + bv0; r1.y = acc[mt][nt][3] + bv1;
            *(float2*)(C + (size_t)row * N + col)       = r0;
            *(float2*)(C + (size_t)(row + 8) * N + col) = r1;
        }
    }
}

__global__ void __launch_bounds__(256) qkv_kernel()
{
    const __half* Wt = (blockIdx.z == 0) ? g_WqT
                     : (blockIdx.z == 1) ? g_WkT : g_WvT;
    float* C = (blockIdx.z == 0) ? g_Q : (blockIdx.z == 1) ? g_K : g_V;
    gemm_fp16_128x256(g_Xh, Wt, C, nullptr);
}

__global__ void __launch_bounds__(256) out_kernel(
    const float* __restrict__ bo, float* __restrict__ out)
{
    gemm_fp16_128x256(g_ctx, g_WoT, out, bo);
}

// ---------------------------------------------------------------------------
// Flash attention, fp16 MMA operands, fp32 scores/softmax.
// 64 q-rows/CTA, 128 thr (4 warps x 16 rows).
// Phase A: S = Q@K^T  (Q,K half [row][d], stride 136 halves)
// Phase B: O += P@V   (P half [i][j] stride 72; Vt half [d][j] stride 72)
// ---------------------------------------------------------------------------
constexpr int QK_STH = 136;   // halves (h2 68: conflict-free frags)
constexpr int PV_STH = 72;    // halves (h2 36: conflict-free frags)
constexpr int SS_STF = 68;    // Ssm float stride

constexpr int OFF_QS = 0;                         // 64*136*2 = 17408
constexpr int OFF_KV = 17408;                     // max(K 17408, Vt 18432)
constexpr int OFF_SS = OFF_KV + 18432;            // 64*68*4 = 17408
constexpr int OFF_PS = OFF_SS + 17408;            // 64*72*2 = 9216
constexpr int OFF_ST = OFF_PS + 9216;             // 3*64*4 = 768
constexpr int ATT_SMEM_BYTES = OFF_ST + 768;      // 63232

__device__ __forceinline__ void load_qk_tile_h(
    const float* __restrict__ gp, __half* __restrict__ dst, int tid)
{
#pragma unroll
    for (int it = 0; it < 16; it++) {
        int idx = tid + it * 128;
        int r   = idx >> 5;
        int c4  = (idx & 31) << 2;
        float4 v = *(const float4*)(gp + (size_t)r * E_ + c4);
        __half2 h0 = __floats2half2_rn(v.x, v.y);
        __half2 h1 = __floats2half2_rn(v.z, v.w);
        uint2 o; o.x = *(uint32_t*)&h0; o.y = *(uint32_t*)&h1;
        *(uint2*)&dst[r * QK_STH + c4] = o;
    }
}

// V loaded TRANSPOSED: Vt[d][j], stride PV_STH halves
__device__ __forceinline__ void load_v_tileT_h(
    const float* __restrict__ gp, __half* __restrict__ dst, int tid)
{
#pragma unroll
    for (int it = 0; it < 16; it++) {
        int idx = tid + it * 128;
        int c   = idx & 127;          // d
        int j0  = (idx >> 7) * 4;     // j group
        __half2 h0 = __floats2half2_rn(gp[(size_t)(j0 + 0) * E_ + c],
                                       gp[(size_t)(j0 + 1) * E_ + c]);
        __half2 h1 = __floats2half2_rn(gp[(size_t)(j0 + 2) * E_ + c],
                                       gp[(size_t)(j0 + 3) * E_ + c]);
        uint2 o; o.x = *(uint32_t*)&h0; o.y = *(uint32_t*)&h1;
        *(uint2*)&dst[c * PV_STH + j0] = o;
    }
}

__global__ void __launch_bounds__(128, 2) attn_kernel()
{
    const int tid  = threadIdx.x;
    const int lane = tid & 31;
    const int warp = tid >> 5;
    const int quad = lane >> 2;
    const int tq   = lane & 3;
    const int mb   = warp * 16;

    const int qt = (gridDim.x - 1) - blockIdx.x;   // heavy tiles first
    const int h  = blockIdx.y;
    const int b  = blockIdx.z;
    const int q0 = qt * 64;

    extern __shared__ char sma[];
    __half* Qs  = (__half*)(sma + OFF_QS);
    __half* KVs = (__half*)(sma + OFF_KV);   // K tile, later Vt
    float*  Ssm = (float*) (sma + OFF_SS);
    __half* Ps  = (__half*)(sma + OFF_PS);
    float*  msr = (float*) (sma + OFF_ST);
    float*  lsr = msr + 64;
    float*  csr = lsr + 64;

    const float slope = exp2f(-0.5f * (float)(h + 1));
    const float inv_s = rsqrtf((float)D_);

    const float* Qp = g_Q + (((size_t)b * S_ + q0) * E_ + (size_t)h * D_);
    load_qk_tile_h(Qp, Qs, tid);
    if (tid < 64) { msr[tid] = -FLT_MAX; lsr[tid] = 0.f; }

    float oc[16][4];
#pragma unroll
    for (int nt = 0; nt < 16; nt++)
#pragma unroll
        for (int r = 0; r < 4; r++) oc[nt][r] = 0.f;

    __syncthreads();

    for (int kt = 0; kt <= qt; kt++) {
        const int k0g = kt * 64;
        const float* Kp = g_K + (((size_t)b * S_ + k0g) * E_ + (size_t)h * D_);
        load_qk_tile_h(Kp, KVs, tid);
        __syncthreads();

        // --- Phase A: S(16x64 per warp) = Q @ K^T, 8 k16 chunks ---
        const uint32_t* Qh2 = (const uint32_t*)Qs;
        const uint32_t* Kh2 = (const uint32_t*)KVs;
        float sc[8][4];
#pragma unroll
        for (int nt = 0; nt < 8; nt++)
#pragma unroll
            for (int r = 0; r < 4; r++) sc[nt][r] = 0.f;

#pragma unroll
        for (int ks = 0; ks < 8; ks++) {
            const int k0 = ks * 8;                    // h2 units
            uint32_t a0 = Qh2[(mb + quad)     * 68 + k0 + tq];
            uint32_t a1 = Qh2[(mb + 8 + quad) * 68 + k0 + tq];
            uint32_t a2 = Qh2[(mb + quad)     * 68 + k0 + 4 + tq];
            uint32_t a3 = Qh2[(mb + 8 + quad) * 68 + k0 + 4 + tq];
#pragma unroll
            for (int nt = 0; nt < 8; nt++) {
                const int nb = nt * 8;
                uint32_t b0 = Kh2[(nb + quad) * 68 + k0 + tq];
                uint32_t b1 = Kh2[(nb + quad) * 68 + k0 + 4 + tq];
                mma_fp16(sc[nt], a0, a1, a2, a3, b0, b1);
            }
        }

        // mask -> +alibi -> scale (reference order), fp32 scores to Ssm
        const int ig0 = q0 + mb + quad;
        const int ig1 = ig0 + 8;
#pragma unroll
        for (int nt = 0; nt < 8; nt++) {
            const int col = nt * 8 + 2 * tq;
            const int jg0 = k0g + col;
#pragma unroll
            for (int e = 0; e < 2; e++) {
                const int jg = jg0 + e;
                float s0 = sc[nt][e];
                float s1 = sc[nt][2 + e];
                if (jg > ig0) s0 = -1e30f;
                if (jg > ig1) s1 = -1e30f;
                s0 = (s0 + slope * (float)(jg - ig0)) * inv_s;
                s1 = (s1 + slope * (float)(jg - ig1)) * inv_s;
                Ssm[(mb + quad)     * SS_STF + col + e] = s0;
                Ssm[(mb + 8 + quad) * SS_STF + col + e] = s1;
            }
        }
        __syncwarp();

        // --- Online softmax (fp32), P rounded to half into Ps ---
        {
            const int r = tid >> 1, p = tid & 1;
            const float* rowS = Ssm + r * SS_STF + p * 32;
            __half* rowP = Ps + r * PV_STH + p * 32;
            float lm = -FLT_MAX;
#pragma unroll 8
            for (int j2 = 0; j2 < 32; j2++) lm = fmaxf(lm, rowS[j2]);
            lm = fmaxf(lm, __shfl_xor_sync(0xffffffffu, lm, 1));
            const float mo = msr[r];
            const float mn = fmaxf(mo, lm);
            const float cc = __expf(mo - mn);
            float s = 0.f;
#pragma unroll 8
            for (int j2 = 0; j2 < 32; j2++) {
                __half ph = __float2half_rn(__expf(rowS[j2] - mn));
                rowP[j2] = ph;
                s += __half2float(ph);      // sum exactly what P@V consumes
            }
            s += __shfl_xor_sync(0xffffffffu, s, 1);
            if (!p) {
                msr[r] = mn;
                lsr[r] = cc * lsr[r] + s;
                csr[r] = cc;
            }
        }
        __syncthreads();   // Phase-A K reads done; Ps/stats published

        // Load V transposed into KVs
        const float* Vp = g_V + (((size_t)b * S_ + k0g) * E_ + (size_t)h * D_);
        load_v_tileT_h(Vp, KVs, tid);
        __syncthreads();

        // --- Phase B: O = c*O + P @ V, 4 k16 chunks ---
        const uint32_t* Ph2 = (const uint32_t*)Ps;
        const uint32_t* Vh2 = (const uint32_t*)KVs;
        const float cr0 = csr[mb + quad];
        const float cr1 = csr[mb + 8 + quad];
#pragma unroll
        for (int nt = 0; nt < 16; nt++) {
            oc[nt][0] *= cr0; oc[nt][1] *= cr0;
            oc[nt][2] *= cr1; oc[nt][3] *= cr1;
        }

#pragma unroll
        for (int kk = 0; kk < 4; kk++) {
            const int k0 = kk * 8;                    // h2 units (j)
            uint32_t a0 = Ph2[(mb + quad)     * 36 + k0 + tq];
            uint32_t a1 = Ph2[(mb + 8 + quad) * 36 + k0 + tq];
            uint32_t a2 = Ph2[(mb + quad)     * 36 + k0 + 4 + tq];
            uint32_t a3 = Ph2[(mb + 8 + quad) * 36 + k0 + 4 + tq];
#pragma unroll
            for (int nt = 0; nt < 16; nt++) {
                const int nb = nt * 8;
                uint32_t b0 = Vh2[(nb + quad) * 36 + k0 + tq];
                uint32_t b1 = Vh2[(nb + quad) * 36 + k0 + 4 + tq];
                mma_fp16(oc[nt], a0, a1, a2, a3, b0, b1);
            }
        }
        __syncthreads();   // protect KVs/Ps before next iteration
    }

    // Final normalize; store ctx as fp16 (consumed directly by out GEMM)
    const float inv0 = 1.0f / lsr[mb + quad];
    const float inv1 = 1.0f / lsr[mb + 8 + quad];
    __half* Op = g_ctx + (((size_t)b * S_ + q0) * E_ + (size_t)h * D_);
    const size_t r0 = (size_t)(mb + quad) * E_;
    const size_t r1 = (size_t)(mb + 8 + quad) * E_;
#pragma unroll
    for (int nt = 0; nt < 16; nt++) {
        const int col = nt * 8 + 2 * tq;
        __half2 v0 = __floats2half2_rn(oc[nt][0] * inv0, oc[nt][1] * inv0);
        __half2 v1 = __floats2half2_rn(oc[nt][2] * inv1, oc[nt][3] * inv1);
        *(uint32_t*)(Op + r0 + col) = *(uint32_t*)&v0;
        *(uint32_t*)(Op + r1 + col) = *(uint32_t*)&v1;
    }
}

// ---------------------------------------------------------------------------
// Launch
// ---------------------------------------------------------------------------
extern "C" void kernel_launch(void* const* d_in, const int* in_sizes, int n_in,
                              void* d_out, int out_size)
{
    const float* x  = (const float*)d_in[0];
    const float* Wq = (const float*)d_in[1];
    const float* Wk = (const float*)d_in[2];
    const float* Wv = (const float*)d_in[3];
    const float* Wo = (const float*)d_in[4];
    const float* bo = (const float*)d_in[5];
    float* out = (float*)d_out;

    (void)in_sizes; (void)n_in; (void)out_size;

    // Pre-pass: x -> fp16; weights -> transposed fp16 [n][k]
    cvt_x_kernel<<<512, 256>>>(x);
    transpose_w_kernel<<<dim3(E_ / 32, E_ / 32, 4), dim3(32, 8)>>>(Wq, Wk, Wv, Wo);

    // smem attributes (>48KB dynamic)
    cudaFuncSetAttribute(qkv_kernel,
                         cudaFuncAttributeMaxDynamicSharedMemorySize,
                         GEMM_SMEM_BYTES);
    cudaFuncSetAttribute(out_kernel,
                         cudaFuncAttributeMaxDynamicSharedMemorySize,
                         GEMM_SMEM_BYTES);
    cudaFuncSetAttribute(attn_kernel,
                         cudaFuncAttributeMaxDynamicSharedMemorySize,
                         ATT_SMEM_BYTES);

    // Fused QKV projections (fp16 mma, 128x256 tiles)
    qkv_kernel<<<dim3(E_ / 256, M_ / 128, 3), 256, GEMM_SMEM_BYTES>>>();

    // Flash attention (fp16 mma, fp32 softmax)
    attn_kernel<<<dim3(S_ / 64, H_, B_), 128, ATT_SMEM_BYTES>>>();

    // Output projection + bias (fp16 mma)
    out_kernel<<<dim3(E_ / 256, M_ / 128, 1), 256, GEMM_SMEM_BYTES>>>(bo, out);
}

// round 14
// speedup vs baseline: 1.5374x; 1.5374x over previous
#include <cuda_runtime.h>
#include <cuda_fp16.h>
#include <cfloat>
#include <cmath>
#include <cstdint>

// Problem constants
constexpr int B_ = 2;
constexpr int S_ = 2048;
constexpr int E_ = 2048;
constexpr int H_ = 16;
constexpr int D_ = 128;
constexpr int M_ = B_ * S_;   // 4096 rows for all GEMMs

// Scratch (static device globals: allowed; no dynamic allocation)
__device__ float g_Q[(size_t)B_ * S_ * E_];
__device__ float g_K[(size_t)B_ * S_ * E_];
__device__ float g_V[(size_t)B_ * S_ * E_];
__device__ __align__(256) __half g_ctx[(size_t)B_ * S_ * E_];   // fp16 ctx
// prepared GEMM inputs (fp16): x row-major [m][k]; weights transposed [n][k]
__device__ __align__(256) __half g_Xh [(size_t)M_ * E_];
__device__ __align__(256) __half g_WqT[(size_t)E_ * E_];
__device__ __align__(256) __half g_WkT[(size_t)E_ * E_];
__device__ __align__(256) __half g_WvT[(size_t)E_ * E_];
__device__ __align__(256) __half g_WoT[(size_t)E_ * E_];

// ---------------------------------------------------------------------------
// helpers
// ---------------------------------------------------------------------------
__device__ __forceinline__ uint32_t f2tf32(float x) {
    uint32_t u;
    asm("cvt.rna.tf32.f32 %0, %1;" : "=r"(u) : "f"(x));
    return u;
}
__device__ __forceinline__ float f2tf32f(float x) {
    return __uint_as_float(f2tf32(x));
}

__device__ __forceinline__ void cp_async16(uint32_t dst, const void* src) {
    asm volatile("cp.async.cg.shared.global [%0], [%1], 16;\n"
                 :: "r"(dst), "l"(src));
}
__device__ __forceinline__ void cp_commit() {
    asm volatile("cp.async.commit_group;\n");
}
template <int N>
__device__ __forceinline__ void cp_wait() {
    asm volatile("cp.async.wait_group %0;\n" :: "n"(N));
}

// fp16 MMA, fp32 accumulate: D(16x8) += A(16x16) * B(16x8)
__device__ __forceinline__ void mma_fp16(
    float* c, uint32_t a0, uint32_t a1, uint32_t a2, uint32_t a3,
    uint32_t b0, uint32_t b1)
{
    asm volatile(
        "mma.sync.aligned.m16n8k16.row.col.f32.f16.f16.f32 "
        "{%0,%1,%2,%3}, {%4,%5,%6,%7}, {%8,%9}, {%0,%1,%2,%3};\n"
        : "+f"(c[0]), "+f"(c[1]), "+f"(c[2]), "+f"(c[3])
        : "r"(a0), "r"(a1), "r"(a2), "r"(a3), "r"(b0), "r"(b1));
}

// tf32 MMA (attention)
__device__ __forceinline__ void mma_tf32(
    float& c0, float& c1, float& c2, float& c3,
    uint32_t a0, uint32_t a1, uint32_t a2, uint32_t a3,
    uint32_t b0, uint32_t b1)
{
    asm volatile(
        "mma.sync.aligned.m16n8k8.row.col.f32.tf32.tf32.f32 "
        "{%0,%1,%2,%3}, {%4,%5,%6,%7}, {%8,%9}, {%0,%1,%2,%3};\n"
        : "+f"(c0), "+f"(c1), "+f"(c2), "+f"(c3)
        : "r"(a0), "r"(a1), "r"(a2), "r"(a3), "r"(b0), "r"(b1));
}

// ---------------------------------------------------------------------------
// Pre-pass: x -> fp16; weights -> transposed [n][k] fp16
// ---------------------------------------------------------------------------
__global__ void __launch_bounds__(256) cvt_x_kernel(const float* __restrict__ x)
{
    const size_t n4 = (size_t)M_ * E_ / 4;
    const size_t stride = (size_t)gridDim.x * blockDim.x;
    for (size_t i = (size_t)blockIdx.x * blockDim.x + threadIdx.x; i < n4;
         i += stride) {
        float4 v = ((const float4*)x)[i];
        __half2 h0 = __floats2half2_rn(v.x, v.y);
        __half2 h1 = __floats2half2_rn(v.z, v.w);
        uint2 o;
        o.x = *(uint32_t*)&h0;
        o.y = *(uint32_t*)&h1;
        ((uint2*)g_Xh)[i] = o;
    }
}

__global__ void __launch_bounds__(256) transpose_w_kernel(
    const float* __restrict__ wq, const float* __restrict__ wk,
    const float* __restrict__ wv, const float* __restrict__ wo)
{
    const float* src; __half* dst;
    switch (blockIdx.z) {
        case 0: src = wq; dst = g_WqT; break;
        case 1: src = wk; dst = g_WkT; break;
        case 2: src = wv; dst = g_WvT; break;
        default: src = wo; dst = g_WoT; break;
    }
    __shared__ float t[32][33];
    const int tx = threadIdx.x, ty = threadIdx.y;
    const int bx = blockIdx.x * 32, by = blockIdx.y * 32;
#pragma unroll
    for (int i = 0; i < 4; i++)
        t[ty + i * 8][tx] = src[(size_t)(by + ty + i * 8) * E_ + bx + tx];
    __syncthreads();
#pragma unroll
    for (int i = 0; i < 4; i++)
        dst[(size_t)(bx + ty + i * 8) * E_ + by + tx] =
            __float2half_rn(t[tx][ty + i * 8]);
}

// ---------------------------------------------------------------------------
// fp16 tensor-core GEMM: C[M,N] = A[M,K] @ Wt^T  (Wt is [N,K] fp16 K-major)
// CTA tile 128x128, 8 warps (wm 0..1 x wn 0..3), warp tile 64x32
// (mt 4 x nt 4 of m16n8k16). BK=32. 3-stage cp.async pipeline.
// Smem rows: 40 halves (80B) -> h2 stride 20, conflict-free frags.
// acc = 64 regs -> ~110 total -> 2 CTAs/SM.
// ---------------------------------------------------------------------------
constexpr int NT_K      = E_ / 32;            // 64 k-tiles
constexpr int AROW_H    = 40;                 // halves per smem row (80B)
constexpr int A_STAGE_B = 128 * AROW_H * 2;   // 10240
constexpr int B_STAGE_B = 128 * AROW_H * 2;   // 10240
constexpr int STAGE_B   = A_STAGE_B + B_STAGE_B;   // 20480
constexpr int NSTG      = 3;
constexpr int GEMM_SMEM_BYTES = NSTG * STAGE_B;    // 61440

__device__ __forceinline__ void gemm_fp16_128x128(
    const __half* __restrict__ A, const __half* __restrict__ Wt,
    float* __restrict__ C, const float* __restrict__ bias)
{
    constexpr int K = E_;
    constexpr int N = E_;
    extern __shared__ char sm8[];
    const uint32_t sb = (uint32_t)__cvta_generic_to_shared(sm8);

    const int tid  = threadIdx.x;
    const int lane = tid & 31;
    const int warp = tid >> 5;
    const int quad = lane >> 2;
    const int tq   = lane & 3;
    const int wm   = warp >> 2;           // 0..1
    const int wn   = warp & 3;            // 0..3
    const int bm0  = blockIdx.y * 128;
    const int bn0  = blockIdx.x * 128;

    float acc[4][4][4];
#pragma unroll
    for (int mt = 0; mt < 4; mt++)
#pragma unroll
        for (int nt = 0; nt < 4; nt++)
#pragma unroll
            for (int r = 0; r < 4; r++) acc[mt][nt][r] = 0.f;

    auto load_tile = [&](int t) {
        const uint32_t so = sb + (uint32_t)((t % NSTG) * STAGE_B);
        const __half* Ag = A  + (size_t)bm0 * K + t * 32;
        const __half* Bg = Wt + (size_t)bn0 * K + t * 32;
#pragma unroll
        for (int i = 0; i < 2; i++) {                 // A: 512 chunks
            int idx = tid + i * 256;
            int r = idx >> 2, c = idx & 3;
            cp_async16(so + r * 80 + c * 16, Ag + (size_t)r * K + c * 8);
        }
#pragma unroll
        for (int i = 0; i < 2; i++) {                 // B: 512 chunks
            int idx = tid + i * 256;
            int r = idx >> 2, c = idx & 3;
            cp_async16(so + A_STAGE_B + r * 80 + c * 16,
                       Bg + (size_t)r * K + c * 8);
        }
        cp_commit();
    };

    load_tile(0);
    load_tile(1);

    for (int t = 0; t < NT_K; t++) {
        if (t + 1 < NT_K) cp_wait<1>(); else cp_wait<0>();
        __syncthreads();
        if (t + 2 < NT_K) load_tile(t + 2);

        const uint32_t* Ah =
            (const uint32_t*)(sm8 + (t % NSTG) * STAGE_B);
        const uint32_t* Bh =
            (const uint32_t*)(sm8 + (t % NSTG) * STAGE_B + A_STAGE_B);

#pragma unroll
        for (int kc = 0; kc < 2; kc++) {               // two k16 chunks
            const int k0 = kc * 8;                     // h2 units
            uint32_t a[4][4], b[4][2];
#pragma unroll
            for (int mt = 0; mt < 4; mt++) {
                const int mb = wm * 64 + mt * 16;
                a[mt][0] = Ah[(mb + quad)     * 20 + k0 + tq];
                a[mt][1] = Ah[(mb + 8 + quad) * 20 + k0 + tq];
                a[mt][2] = Ah[(mb + quad)     * 20 + k0 + 4 + tq];
                a[mt][3] = Ah[(mb + 8 + quad) * 20 + k0 + 4 + tq];
            }
#pragma unroll
            for (int nt = 0; nt < 4; nt++) {
                const int nb = wn * 32 + nt * 8;
                b[nt][0] = Bh[(nb + quad) * 20 + k0 + tq];
                b[nt][1] = Bh[(nb + quad) * 20 + k0 + 4 + tq];
            }
#pragma unroll
            for (int mt = 0; mt < 4; mt++)
#pragma unroll
                for (int nt = 0; nt < 4; nt++)
                    mma_fp16(acc[mt][nt],
                             a[mt][0], a[mt][1], a[mt][2], a[mt][3],
                             b[nt][0], b[nt][1]);
        }
    }

    // Epilogue
#pragma unroll
    for (int mt = 0; mt < 4; mt++) {
        const int row = bm0 + wm * 64 + mt * 16 + quad;
#pragma unroll
        for (int nt = 0; nt < 4; nt++) {
            const int col = bn0 + wn * 32 + nt * 8 + 2 * tq;
            float bv0 = bias ? bias[col]     : 0.f;
            float bv1 = bias ? bias[col + 1] : 0.f;
            float2 r0, r1;
            r0.x = acc[mt][nt][0] + bv0; r0.y = acc[mt][nt][1] + bv1;
            r1.x = acc[mt][nt][2] + bv0; r1.y = acc[mt][nt][3] + bv1;
            *(float2*)(C + (size_t)row * N + col)       = r0;
            *(float2*)(C + (size_t)(row + 8) * N + col) = r1;
        }
    }
}

__global__ void __launch_bounds__(256, 2) qkv_kernel()
{
    const __half* Wt = (blockIdx.z == 0) ? g_WqT
                     : (blockIdx.z == 1) ? g_WkT : g_WvT;
    float* C = (blockIdx.z == 0) ? g_Q : (blockIdx.z == 1) ? g_K : g_V;
    gemm_fp16_128x128(g_Xh, Wt, C, nullptr);
}

__global__ void __launch_bounds__(256, 2) out_kernel(
    const float* __restrict__ bo, float* __restrict__ out)
{
    gemm_fp16_128x128(g_ctx, g_WoT, out, bo);
}

// ---------------------------------------------------------------------------
// Flash attention with tf32 mma.sync (R10 version, proven fast) —
// only change: epilogue stores ctx as fp16 for the out GEMM.
// ---------------------------------------------------------------------------
constexpr int QS_ST = 132;
constexpr int VT_ST = 68;
constexpr int OFF_Q   = 0;
constexpr int OFF_KV  = OFF_Q + 64 * QS_ST;
constexpr int OFF_S   = OFF_KV + 128 * VT_ST;
constexpr int OFF_M   = OFF_S + 64 * VT_ST;
constexpr int OFF_L   = OFF_M + 64;
constexpr int OFF_C   = OFF_L + 64;
constexpr int ATT_SMEM_FLOATS = OFF_C + 64;
constexpr int ATT_SMEM_BYTES  = ATT_SMEM_FLOATS * 4;  // 86784

__device__ __forceinline__ void load_qk_tile(
    const float* __restrict__ gp, float* __restrict__ dst, int tid)
{
#pragma unroll
    for (int it = 0; it < 16; it++) {
        int idx = tid + it * 128;
        int r   = idx >> 5;
        int c4  = (idx & 31) << 2;
        float4 v = *(const float4*)(gp + (size_t)r * E_ + c4);
        float4 o;
        o.x = f2tf32f(v.x); o.y = f2tf32f(v.y);
        o.z = f2tf32f(v.z); o.w = f2tf32f(v.w);
        *(float4*)&dst[r * QS_ST + c4] = o;
    }
}

__device__ __forceinline__ void load_v_tileT(
    const float* __restrict__ gp, float* __restrict__ dst, int tid)
{
#pragma unroll
    for (int it = 0; it < 16; it++) {
        int idx = tid + it * 128;
        int c   = idx & 127;
        int j0  = (idx >> 7) * 4;
        float4 o;
        o.x = f2tf32f(gp[(size_t)(j0 + 0) * E_ + c]);
        o.y = f2tf32f(gp[(size_t)(j0 + 1) * E_ + c]);
        o.z = f2tf32f(gp[(size_t)(j0 + 2) * E_ + c]);
        o.w = f2tf32f(gp[(size_t)(j0 + 3) * E_ + c]);
        *(float4*)&dst[c * VT_ST + j0] = o;
    }
}

__global__ void __launch_bounds__(128, 2) attn_kernel()
{
    const int tid  = threadIdx.x;
    const int lane = tid & 31;
    const int warp = tid >> 5;
    const int quad = lane >> 2;
    const int tq   = lane & 3;
    const int mb   = warp * 16;

    const int qt = (gridDim.x - 1) - blockIdx.x;   // heavy tiles first
    const int h  = blockIdx.y;
    const int b  = blockIdx.z;
    const int q0 = qt * 64;

    extern __shared__ float sm[];
    float* Qs  = sm + OFF_Q;
    float* KVs = sm + OFF_KV;
    float* Ssm = sm + OFF_S;
    float* msr = sm + OFF_M;
    float* lsr = sm + OFF_L;
    float* csr = sm + OFF_C;

    const float slope = exp2f(-0.5f * (float)(h + 1));
    const float inv_s = rsqrtf((float)D_);

    const float* Qp = g_Q + (((size_t)b * S_ + q0) * E_ + (size_t)h * D_);
    load_qk_tile(Qp, Qs, tid);
    if (tid < 64) { msr[tid] = -FLT_MAX; lsr[tid] = 0.f; }

    float oc[16][4];
#pragma unroll
    for (int nt = 0; nt < 16; nt++)
#pragma unroll
        for (int r = 0; r < 4; r++) oc[nt][r] = 0.f;

    __syncthreads();

    for (int kt = 0; kt <= qt; kt++) {
        const int k0g = kt * 64;
        const float* Kp = g_K + (((size_t)b * S_ + k0g) * E_ + (size_t)h * D_);
        load_qk_tile(Kp, KVs, tid);
        __syncthreads();

        // --- Phase A: S(16x64 per warp) = Q @ K^T ---
        float sc[8][4];
#pragma unroll
        for (int nt = 0; nt < 8; nt++)
#pragma unroll
            for (int r = 0; r < 4; r++) sc[nt][r] = 0.f;

#pragma unroll
        for (int ks = 0; ks < 16; ks++) {
            const int k0 = ks * 8;
            uint32_t a[4], bb[8][2];
            a[0] = __float_as_uint(Qs[(mb + quad)     * QS_ST + k0 + tq]);
            a[1] = __float_as_uint(Qs[(mb + 8 + quad) * QS_ST + k0 + tq]);
            a[2] = __float_as_uint(Qs[(mb + quad)     * QS_ST + k0 + 4 + tq]);
            a[3] = __float_as_uint(Qs[(mb + 8 + quad) * QS_ST + k0 + 4 + tq]);
#pragma unroll
            for (int nt = 0; nt < 8; nt++) {
                const int nb = nt * 8;
                bb[nt][0] = __float_as_uint(KVs[(nb + quad) * QS_ST + k0 + tq]);
                bb[nt][1] = __float_as_uint(KVs[(nb + quad) * QS_ST + k0 + 4 + tq]);
            }
#pragma unroll
            for (int nt = 0; nt < 8; nt++)
                mma_tf32(sc[nt][0], sc[nt][1], sc[nt][2], sc[nt][3],
                         a[0], a[1], a[2], a[3], bb[nt][0], bb[nt][1]);
        }

        // mask -> +alibi -> scale (reference order)
        const int ig0 = q0 + mb + quad;
        const int ig1 = ig0 + 8;
#pragma unroll
        for (int nt = 0; nt < 8; nt++) {
            const int col = nt * 8 + 2 * tq;
            const int jg0 = k0g + col;
#pragma unroll
            for (int e = 0; e < 2; e++) {
                const int jg = jg0 + e;
                float s0 = sc[nt][e];
                float s1 = sc[nt][2 + e];
                if (jg > ig0) s0 = -1e30f;
                if (jg > ig1) s1 = -1e30f;
                s0 = (s0 + slope * (float)(jg - ig0)) * inv_s;
                s1 = (s1 + slope * (float)(jg - ig1)) * inv_s;
                Ssm[(mb + quad)     * VT_ST + col + e] = s0;
                Ssm[(mb + 8 + quad) * VT_ST + col + e] = s1;
            }
        }
        __syncwarp();

        // --- Online softmax: 2 threads per row ---
        {
            const int r = tid >> 1, p = tid & 1;
            float* row = Ssm + r * VT_ST + p * 32;
            float lm = -FLT_MAX;
#pragma unroll 8
            for (int j2 = 0; j2 < 32; j2++) lm = fmaxf(lm, row[j2]);
            lm = fmaxf(lm, __shfl_xor_sync(0xffffffffu, lm, 1));
            const float mo = msr[r];
            const float mn = fmaxf(mo, lm);
            const float cc = __expf(mo - mn);
            float s = 0.f;
#pragma unroll 8
            for (int j2 = 0; j2 < 32; j2++) {
                float pv = __expf(row[j2] - mn);
                pv = f2tf32f(pv);
                row[j2] = pv;
                s += pv;
            }
            s += __shfl_xor_sync(0xffffffffu, s, 1);
            if (!p) {
                msr[r] = mn;
                lsr[r] = cc * lsr[r] + s;
                csr[r] = cc;
            }
        }
        __syncthreads();

        // Load V transposed
        const float* Vp = g_V + (((size_t)b * S_ + k0g) * E_ + (size_t)h * D_);
        load_v_tileT(Vp, KVs, tid);
        __syncthreads();

        // --- Phase B: O = c*O + P @ V ---
        const float cr0 = csr[mb + quad];
        const float cr1 = csr[mb + 8 + quad];
#pragma unroll
        for (int nt = 0; nt < 16; nt++) {
            oc[nt][0] *= cr0; oc[nt][1] *= cr0;
            oc[nt][2] *= cr1; oc[nt][3] *= cr1;
        }

#pragma unroll
        for (int kk = 0; kk < 8; kk++) {
            const int k0 = kk * 8;
            uint32_t a[4];
            a[0] = __float_as_uint(Ssm[(mb + quad)     * VT_ST + k0 + tq]);
            a[1] = __float_as_uint(Ssm[(mb + 8 + quad) * VT_ST + k0 + tq]);
            a[2] = __float_as_uint(Ssm[(mb + quad)     * VT_ST + k0 + 4 + tq]);
            a[3] = __float_as_uint(Ssm[(mb + 8 + quad) * VT_ST + k0 + 4 + tq]);
#pragma unroll
            for (int nt = 0; nt < 16; nt++) {
                const int nb = nt * 8;
                uint32_t b0 = __float_as_uint(KVs[(nb + quad) * VT_ST + k0 + tq]);
                uint32_t b1 = __float_as_uint(KVs[(nb + quad) * VT_ST + k0 + 4 + tq]);
                mma_tf32(oc[nt][0], oc[nt][1], oc[nt][2], oc[nt][3],
                         a[0], a[1], a[2], a[3], b0, b1);
            }
        }
        __syncthreads();
    }

    // Final normalize; store ctx as fp16 (consumed directly by out GEMM)
    const float inv0 = 1.0f / lsr[mb + quad];
    const float inv1 = 1.0f / lsr[mb + 8 + quad];
    __half* Op = g_ctx + (((size_t)b * S_ + q0) * E_ + (size_t)h * D_);
    const size_t r0 = (size_t)(mb + quad) * E_;
    const size_t r1 = (size_t)(mb + 8 + quad) * E_;
#pragma unroll
    for (int nt = 0; nt < 16; nt++) {
        const int col = nt * 8 + 2 * tq;
        __half2 v0 = __floats2half2_rn(oc[nt][0] * inv0, oc[nt][1] * inv0);
        __half2 v1 = __floats2half2_rn(oc[nt][2] * inv1, oc[nt][3] * inv1);
        *(uint32_t*)(Op + r0 + col) = *(uint32_t*)&v0;
        *(uint32_t*)(Op + r1 + col) = *(uint32_t*)&v1;
    }
}

// ---------------------------------------------------------------------------
// Launch
// ---------------------------------------------------------------------------
extern "C" void kernel_launch(void* const* d_in, const int* in_sizes, int n_in,
                              void* d_out, int out_size)
{
    const float* x  = (const float*)d_in[0];
    const float* Wq = (const float*)d_in[1];
    const float* Wk = (const float*)d_in[2];
    const float* Wv = (const float*)d_in[3];
    const float* Wo = (const float*)d_in[4];
    const float* bo = (const float*)d_in[5];
    float* out = (float*)d_out;

    (void)in_sizes; (void)n_in; (void)out_size;

    // Pre-pass: x -> fp16; weights -> transposed fp16 [n][k]
    cvt_x_kernel<<<512, 256>>>(x);
    transpose_w_kernel<<<dim3(E_ / 32, E_ / 32, 4), dim3(32, 8)>>>(Wq, Wk, Wv, Wo);

    // smem attributes (>48KB dynamic)
    cudaFuncSetAttribute(qkv_kernel,
                         cudaFuncAttributeMaxDynamicSharedMemorySize,
                         GEMM_SMEM_BYTES);
    cudaFuncSetAttribute(out_kernel,
                         cudaFuncAttributeMaxDynamicSharedMemorySize,
                         GEMM_SMEM_BYTES);
    cudaFuncSetAttribute(attn_kernel,
                         cudaFuncAttributeMaxDynamicSharedMemorySize,
                         ATT_SMEM_BYTES);

    // Fused QKV projections (fp16 mma, 128x128 tiles, 2 CTAs/SM)
    qkv_kernel<<<dim3(E_ / 128, M_ / 128, 3), 256, GEMM_SMEM_BYTES>>>();

    // Flash attention (tf32 mma, fp32 softmax)
    attn_kernel<<<dim3(S_ / 64, H_, B_), 128, ATT_SMEM_BYTES>>>();

    // Output projection + bias (fp16 mma)
    out_kernel<<<dim3(E_ / 128, M_ / 128, 1), 256, GEMM_SMEM_BYTES>>>(bo, out);
}

// round 16
// speedup vs baseline: 1.5579x; 1.0134x over previous
#include <cuda_runtime.h>
#include <cuda_fp16.h>
#include <cfloat>
#include <cmath>
#include <cstdint>

// Problem constants
constexpr int B_ = 2;
constexpr int S_ = 2048;
constexpr int E_ = 2048;
constexpr int H_ = 16;
constexpr int D_ = 128;
constexpr int M_ = B_ * S_;   // 4096 rows for all GEMMs

// Scratch (static device globals: allowed; no dynamic allocation)
__device__ float g_Q[(size_t)B_ * S_ * E_];
__device__ float g_K[(size_t)B_ * S_ * E_];
__device__ float g_V[(size_t)B_ * S_ * E_];
__device__ float g_VT[(size_t)B_ * H_ * D_ * S_];               // V transposed [bh][d][s]
__device__ __align__(256) __half g_ctx[(size_t)B_ * S_ * E_];   // fp16 ctx
// prepared GEMM inputs (fp16): x row-major [m][k]; weights transposed [n][k]
__device__ __align__(256) __half g_Xh [(size_t)M_ * E_];
__device__ __align__(256) __half g_WqT[(size_t)E_ * E_];
__device__ __align__(256) __half g_WkT[(size_t)E_ * E_];
__device__ __align__(256) __half g_WvT[(size_t)E_ * E_];
__device__ __align__(256) __half g_WoT[(size_t)E_ * E_];

// ---------------------------------------------------------------------------
// helpers
// ---------------------------------------------------------------------------
__device__ __forceinline__ uint32_t f2tf32(float x) {
    uint32_t u;
    asm("cvt.rna.tf32.f32 %0, %1;" : "=r"(u) : "f"(x));
    return u;
}
__device__ __forceinline__ float f2tf32f(float x) {
    return __uint_as_float(f2tf32(x));
}

__device__ __forceinline__ void cp_async16(uint32_t dst, const void* src) {
    asm volatile("cp.async.cg.shared.global [%0], [%1], 16;\n"
                 :: "r"(dst), "l"(src));
}
__device__ __forceinline__ void cp_commit() {
    asm volatile("cp.async.commit_group;\n");
}
template <int N>
__device__ __forceinline__ void cp_wait() {
    asm volatile("cp.async.wait_group %0;\n" :: "n"(N));
}

// fp16 MMA, fp32 accumulate: D(16x8) += A(16x16) * B(16x8)
__device__ __forceinline__ void mma_fp16(
    float* c, uint32_t a0, uint32_t a1, uint32_t a2, uint32_t a3,
    uint32_t b0, uint32_t b1)
{
    asm volatile(
        "mma.sync.aligned.m16n8k16.row.col.f32.f16.f16.f32 "
        "{%0,%1,%2,%3}, {%4,%5,%6,%7}, {%8,%9}, {%0,%1,%2,%3};\n"
        : "+f"(c[0]), "+f"(c[1]), "+f"(c[2]), "+f"(c[3])
        : "r"(a0), "r"(a1), "r"(a2), "r"(a3), "r"(b0), "r"(b1));
}

// tf32 MMA (attention)
__device__ __forceinline__ void mma_tf32(
    float& c0, float& c1, float& c2, float& c3,
    uint32_t a0, uint32_t a1, uint32_t a2, uint32_t a3,
    uint32_t b0, uint32_t b1)
{
    asm volatile(
        "mma.sync.aligned.m16n8k8.row.col.f32.tf32.tf32.f32 "
        "{%0,%1,%2,%3}, {%4,%5,%6,%7}, {%8,%9}, {%0,%1,%2,%3};\n"
        : "+f"(c0), "+f"(c1), "+f"(c2), "+f"(c3)
        : "r"(a0), "r"(a1), "r"(a2), "r"(a3), "r"(b0), "r"(b1));
}

// ---------------------------------------------------------------------------
// Pre-pass: x -> fp16; weights -> transposed [n][k] fp16
// ---------------------------------------------------------------------------
__global__ void __launch_bounds__(256) cvt_x_kernel(const float* __restrict__ x)
{
    const size_t n4 = (size_t)M_ * E_ / 4;
    const size_t stride = (size_t)gridDim.x * blockDim.x;
    for (size_t i = (size_t)blockIdx.x * blockDim.x + threadIdx.x; i < n4;
         i += stride) {
        float4 v = ((const float4*)x)[i];
        __half2 h0 = __floats2half2_rn(v.x, v.y);
        __half2 h1 = __floats2half2_rn(v.z, v.w);
        uint2 o;
        o.x = *(uint32_t*)&h0;
        o.y = *(uint32_t*)&h1;
        ((uint2*)g_Xh)[i] = o;
    }
}

__global__ void __launch_bounds__(256) transpose_w_kernel(
    const float* __restrict__ wq, const float* __restrict__ wk,
    const float* __restrict__ wv, const float* __restrict__ wo)
{
    const float* src; __half* dst;
    switch (blockIdx.z) {
        case 0: src = wq; dst = g_WqT; break;
        case 1: src = wk; dst = g_WkT; break;
        case 2: src = wv; dst = g_WvT; break;
        default: src = wo; dst = g_WoT; break;
    }
    __shared__ float t[32][33];
    const int tx = threadIdx.x, ty = threadIdx.y;
    const int bx = blockIdx.x * 32, by = blockIdx.y * 32;
#pragma unroll
    for (int i = 0; i < 4; i++)
        t[ty + i * 8][tx] = src[(size_t)(by + ty + i * 8) * E_ + bx + tx];
    __syncthreads();
#pragma unroll
    for (int i = 0; i < 4; i++)
        dst[(size_t)(bx + ty + i * 8) * E_ + by + tx] =
            __float2half_rn(t[tx][ty + i * 8]);
}

// Transpose V (after qkv): g_VT[bh][d][s] = g_V[b][s][h*128+d] (already tf32)
__global__ void __launch_bounds__(256) transpose_v_kernel()
{
    const int bh = blockIdx.z;            // b*16+h
    const int b  = bh >> 4;
    const int h  = bh & 15;
    __shared__ float t[32][33];
    const int tx = threadIdx.x, ty = threadIdx.y;
    const int s0 = blockIdx.x * 32, d0 = blockIdx.y * 32;
#pragma unroll
    for (int i = 0; i < 4; i++)
        t[ty + i * 8][tx] =
            g_V[((size_t)(b * S_ + s0 + ty + i * 8)) * E_ + h * D_ + d0 + tx];
    __syncthreads();
#pragma unroll
    for (int i = 0; i < 4; i++)
        g_VT[((size_t)bh * D_ + d0 + ty + i * 8) * S_ + s0 + tx] =
            t[tx][ty + i * 8];
}

// ---------------------------------------------------------------------------
// fp16 tensor-core GEMM: C[M,N] = A[M,K] @ Wt^T  (Wt is [N,K] fp16 K-major)
// CTA tile 128x128, 8 warps, warp tile 64x32. BK=32, 3-stage cp.async.
// ROUND: round outputs to tf32 (Q/K/V feeding the tf32 attention).
// ---------------------------------------------------------------------------
constexpr int NT_K      = E_ / 32;
constexpr int AROW_H    = 40;
constexpr int A_STAGE_B = 128 * AROW_H * 2;        // 10240
constexpr int B_STAGE_B = 128 * AROW_H * 2;        // 10240
constexpr int STAGE_B   = A_STAGE_B + B_STAGE_B;   // 20480
constexpr int NSTG      = 3;
constexpr int GEMM_SMEM_BYTES = NSTG * STAGE_B;    // 61440

template <bool ROUND>
__device__ __forceinline__ void gemm_fp16_128x128(
    const __half* __restrict__ A, const __half* __restrict__ Wt,
    float* __restrict__ C, const float* __restrict__ bias)
{
    constexpr int K = E_;
    constexpr int N = E_;
    extern __shared__ char sm8[];
    const uint32_t sb = (uint32_t)__cvta_generic_to_shared(sm8);

    const int tid  = threadIdx.x;
    const int lane = tid & 31;
    const int warp = tid >> 5;
    const int quad = lane >> 2;
    const int tq   = lane & 3;
    const int wm   = warp >> 2;
    const int wn   = warp & 3;
    const int bm0  = blockIdx.y * 128;
    const int bn0  = blockIdx.x * 128;

    float acc[4][4][4];
#pragma unroll
    for (int mt = 0; mt < 4; mt++)
#pragma unroll
        for (int nt = 0; nt < 4; nt++)
#pragma unroll
            for (int r = 0; r < 4; r++) acc[mt][nt][r] = 0.f;

    auto load_tile = [&](int t) {
        const uint32_t so = sb + (uint32_t)((t % NSTG) * STAGE_B);
        const __half* Ag = A  + (size_t)bm0 * K + t * 32;
        const __half* Bg = Wt + (size_t)bn0 * K + t * 32;
#pragma unroll
        for (int i = 0; i < 2; i++) {
            int idx = tid + i * 256;
            int r = idx >> 2, c = idx & 3;
            cp_async16(so + r * 80 + c * 16, Ag + (size_t)r * K + c * 8);
        }
#pragma unroll
        for (int i = 0; i < 2; i++) {
            int idx = tid + i * 256;
            int r = idx >> 2, c = idx & 3;
            cp_async16(so + A_STAGE_B + r * 80 + c * 16,
                       Bg + (size_t)r * K + c * 8);
        }
        cp_commit();
    };

    load_tile(0);
    load_tile(1);

    for (int t = 0; t < NT_K; t++) {
        if (t + 1 < NT_K) cp_wait<1>(); else cp_wait<0>();
        __syncthreads();
        if (t + 2 < NT_K) load_tile(t + 2);

        const uint32_t* Ah =
            (const uint32_t*)(sm8 + (t % NSTG) * STAGE_B);
        const uint32_t* Bh =
            (const uint32_t*)(sm8 + (t % NSTG) * STAGE_B + A_STAGE_B);

#pragma unroll
        for (int kc = 0; kc < 2; kc++) {
            const int k0 = kc * 8;
            uint32_t a[4][4], b[4][2];
#pragma unroll
            for (int mt = 0; mt < 4; mt++) {
                const int mb = wm * 64 + mt * 16;
                a[mt][0] = Ah[(mb + quad)     * 20 + k0 + tq];
                a[mt][1] = Ah[(mb + 8 + quad) * 20 + k0 + tq];
                a[mt][2] = Ah[(mb + quad)     * 20 + k0 + 4 + tq];
                a[mt][3] = Ah[(mb + 8 + quad) * 20 + k0 + 4 + tq];
            }
#pragma unroll
            for (int nt = 0; nt < 4; nt++) {
                const int nb = wn * 32 + nt * 8;
                b[nt][0] = Bh[(nb + quad) * 20 + k0 + tq];
                b[nt][1] = Bh[(nb + quad) * 20 + k0 + 4 + tq];
            }
#pragma unroll
            for (int mt = 0; mt < 4; mt++)
#pragma unroll
                for (int nt = 0; nt < 4; nt++)
                    mma_fp16(acc[mt][nt],
                             a[mt][0], a[mt][1], a[mt][2], a[mt][3],
                             b[nt][0], b[nt][1]);
        }
    }

    // Epilogue
#pragma unroll
    for (int mt = 0; mt < 4; mt++) {
        const int row = bm0 + wm * 64 + mt * 16 + quad;
#pragma unroll
        for (int nt = 0; nt < 4; nt++) {
            const int col = bn0 + wn * 32 + nt * 8 + 2 * tq;
            float bv0 = bias ? bias[col]     : 0.f;
            float bv1 = bias ? bias[col + 1] : 0.f;
            float2 r0, r1;
            r0.x = acc[mt][nt][0] + bv0; r0.y = acc[mt][nt][1] + bv1;
            r1.x = acc[mt][nt][2] + bv0; r1.y = acc[mt][nt][3] + bv1;
            if (ROUND) {
                r0.x = f2tf32f(r0.x); r0.y = f2tf32f(r0.y);
                r1.x = f2tf32f(r1.x); r1.y = f2tf32f(r1.y);
            }
            *(float2*)(C + (size_t)row * N + col)       = r0;
            *(float2*)(C + (size_t)(row + 8) * N + col) = r1;
        }
    }
}

__global__ void __launch_bounds__(256, 2) qkv_kernel()
{
    const __half* Wt = (blockIdx.z == 0) ? g_WqT
                     : (blockIdx.z == 1) ? g_WkT : g_WvT;
    float* C = (blockIdx.z == 0) ? g_Q : (blockIdx.z == 1) ? g_K : g_V;
    gemm_fp16_128x128<true>(g_Xh, Wt, C, nullptr);   // tf32-rounded outputs
}

__global__ void __launch_bounds__(256, 2) out_kernel(
    const float* __restrict__ bo, float* __restrict__ out)
{
    gemm_fp16_128x128<false>(g_ctx, g_WoT, out, bo);
}

// ---------------------------------------------------------------------------
// Flash attention with tf32 mma.sync — R14 structure verbatim (synchronous
// loads, proven), with three safe changes:
//   (1) Q/K/V already tf32-rounded -> tile loads are pure float4 copies
//   (2) V loaded from pre-transposed g_VT (float4, no scalar gather)
//   (3) each CTA processes q-tile pair (qt, 31-qt): uniform 33 k-tiles
// ---------------------------------------------------------------------------
constexpr int QS_ST = 132;
constexpr int VT_ST = 68;
constexpr int OFF_Q   = 0;
constexpr int OFF_KV  = OFF_Q + 64 * QS_ST;
constexpr int OFF_S   = OFF_KV + 128 * VT_ST;
constexpr int OFF_M   = OFF_S + 64 * VT_ST;
constexpr int OFF_L   = OFF_M + 64;
constexpr int OFF_C   = OFF_L + 64;
constexpr int ATT_SMEM_FLOATS = OFF_C + 64;
constexpr int ATT_SMEM_BYTES  = ATT_SMEM_FLOATS * 4;  // 86784

// 64x128 tile, pure copy (data already tf32-rounded)
__device__ __forceinline__ void load_qk_tile(
    const float* __restrict__ gp, float* __restrict__ dst, int tid)
{
#pragma unroll
    for (int it = 0; it < 16; it++) {
        int idx = tid + it * 128;
        int r   = idx >> 5;
        int c4  = (idx & 31) << 2;
        *(float4*)&dst[r * QS_ST + c4] =
            *(const float4*)(gp + (size_t)r * E_ + c4);
    }
}

// Vt tile [128 d][64 j] from g_VT[bh][d][s] (row stride S_), pure float4 copy
__device__ __forceinline__ void load_v_tileT(
    const float* __restrict__ gp, float* __restrict__ dst, int tid)
{
#pragma unroll
    for (int it = 0; it < 16; it++) {
        int idx = tid + it * 128;
        int d   = idx >> 4;           // 0..127
        int j0  = (idx & 15) << 2;    // 0..60
        *(float4*)&dst[d * VT_ST + j0] =
            *(const float4*)(gp + (size_t)d * S_ + j0);
    }
}

__global__ void __launch_bounds__(128, 2) attn_kernel()
{
    const int tid  = threadIdx.x;
    const int lane = tid & 31;
    const int warp = tid >> 5;
    const int quad = lane >> 2;
    const int tq   = lane & 3;
    const int mb   = warp * 16;

    const int h  = blockIdx.y;
    const int b  = blockIdx.z;
    const int bh = b * H_ + h;
    constexpr int NQT = S_ / 64;     // 32

    extern __shared__ float sm[];
    float* Qs  = sm + OFF_Q;
    float* KVs = sm + OFF_KV;
    float* Ssm = sm + OFF_S;
    float* msr = sm + OFF_M;
    float* lsr = sm + OFF_L;
    float* csr = sm + OFF_C;

    const float slope = exp2f(-0.5f * (float)(h + 1));
    const float inv_s = rsqrtf((float)D_);

    for (int pi = 0; pi < 2; pi++) {
        const int qt = pi ? (NQT - 1 - (int)blockIdx.x) : (int)blockIdx.x;
        const int q0 = qt * 64;

        __syncthreads();   // guard stats/Qs re-init vs previous pi epilogue

        const float* Qp = g_Q + (((size_t)b * S_ + q0) * E_ + (size_t)h * D_);
        load_qk_tile(Qp, Qs, tid);
        if (tid < 64) { msr[tid] = -FLT_MAX; lsr[tid] = 0.f; }

        float oc[16][4];
#pragma unroll
        for (int nt = 0; nt < 16; nt++)
#pragma unroll
            for (int r = 0; r < 4; r++) oc[nt][r] = 0.f;

        __syncthreads();

        for (int kt = 0; kt <= qt; kt++) {
            const int k0g = kt * 64;
            const float* Kp =
                g_K + (((size_t)b * S_ + k0g) * E_ + (size_t)h * D_);
            load_qk_tile(Kp, KVs, tid);
            __syncthreads();

            // --- Phase A: S(16x64 per warp) = Q @ K^T ---
            float sc[8][4];
#pragma unroll
            for (int nt = 0; nt < 8; nt++)
#pragma unroll
                for (int r = 0; r < 4; r++) sc[nt][r] = 0.f;

#pragma unroll
            for (int ks = 0; ks < 16; ks++) {
                const int k0 = ks * 8;
                uint32_t a[4], bb[8][2];
                a[0] = __float_as_uint(Qs[(mb + quad)     * QS_ST + k0 + tq]);
                a[1] = __float_as_uint(Qs[(mb + 8 + quad) * QS_ST + k0 + tq]);
                a[2] = __float_as_uint(Qs[(mb + quad)     * QS_ST + k0 + 4 + tq]);
                a[3] = __float_as_uint(Qs[(mb + 8 + quad) * QS_ST + k0 + 4 + tq]);
#pragma unroll
                for (int nt = 0; nt < 8; nt++) {
                    const int nb = nt * 8;
                    bb[nt][0] = __float_as_uint(KVs[(nb + quad) * QS_ST + k0 + tq]);
                    bb[nt][1] = __float_as_uint(KVs[(nb + quad) * QS_ST + k0 + 4 + tq]);
                }
#pragma unroll
                for (int nt = 0; nt < 8; nt++)
                    mma_tf32(sc[nt][0], sc[nt][1], sc[nt][2], sc[nt][3],
                             a[0], a[1], a[2], a[3], bb[nt][0], bb[nt][1]);
            }

            // mask -> +alibi -> scale (reference order)
            const int ig0 = q0 + mb + quad;
            const int ig1 = ig0 + 8;
#pragma unroll
            for (int nt = 0; nt < 8; nt++) {
                const int col = nt * 8 + 2 * tq;
                const int jg0 = k0g + col;
#pragma unroll
                for (int e = 0; e < 2; e++) {
                    const int jg = jg0 + e;
                    float s0 = sc[nt][e];
                    float s1 = sc[nt][2 + e];
                    if (jg > ig0) s0 = -1e30f;
                    if (jg > ig1) s1 = -1e30f;
                    s0 = (s0 + slope * (float)(jg - ig0)) * inv_s;
                    s1 = (s1 + slope * (float)(jg - ig1)) * inv_s;
                    Ssm[(mb + quad)     * VT_ST + col + e] = s0;
                    Ssm[(mb + 8 + quad) * VT_ST + col + e] = s1;
                }
            }
            __syncwarp();

            // --- Online softmax: 2 threads per row (own warp's rows) ---
            {
                const int r = tid >> 1, p = tid & 1;
                float* row = Ssm + r * VT_ST + p * 32;
                float lm = -FLT_MAX;
#pragma unroll 8
                for (int j2 = 0; j2 < 32; j2++) lm = fmaxf(lm, row[j2]);
                lm = fmaxf(lm, __shfl_xor_sync(0xffffffffu, lm, 1));
                const float mo = msr[r];
                const float mn = fmaxf(mo, lm);
                const float cc = __expf(mo - mn);
                float s = 0.f;
#pragma unroll 8
                for (int j2 = 0; j2 < 32; j2++) {
                    float pv = __expf(row[j2] - mn);
                    pv = f2tf32f(pv);
                    row[j2] = pv;
                    s += pv;
                }
                s += __shfl_xor_sync(0xffffffffu, s, 1);
                if (!p) {
                    msr[r] = mn;
                    lsr[r] = cc * lsr[r] + s;
                    csr[r] = cc;
                }
            }
            __syncthreads();

            // Load V (pre-transposed) into KVs
            const float* Vp = g_VT + ((size_t)bh * D_) * S_ + k0g;
            load_v_tileT(Vp, KVs, tid);
            __syncthreads();

            // --- Phase B: O = c*O + P @ V ---
            const float cr0 = csr[mb + quad];
            const float cr1 = csr[mb + 8 + quad];
#pragma unroll
            for (int nt = 0; nt < 16; nt++) {
                oc[nt][0] *= cr0; oc[nt][1] *= cr0;
                oc[nt][2] *= cr1; oc[nt][3] *= cr1;
            }

#pragma unroll
            for (int kk = 0; kk < 8; kk++) {
                const int k0 = kk * 8;
                uint32_t a0 = __float_as_uint(Ssm[(mb + quad)     * VT_ST + k0 + tq]);
                uint32_t a1 = __float_as_uint(Ssm[(mb + 8 + quad) * VT_ST + k0 + tq]);
                uint32_t a2 = __float_as_uint(Ssm[(mb + quad)     * VT_ST + k0 + 4 + tq]);
                uint32_t a3 = __float_as_uint(Ssm[(mb + 8 + quad) * VT_ST + k0 + 4 + tq]);
#pragma unroll
                for (int nt = 0; nt < 16; nt++) {
                    const int nb = nt * 8;
                    uint32_t b0 = __float_as_uint(KVs[(nb + quad) * VT_ST + k0 + tq]);
                    uint32_t b1 = __float_as_uint(KVs[(nb + quad) * VT_ST + k0 + 4 + tq]);
                    mma_tf32(oc[nt][0], oc[nt][1], oc[nt][2], oc[nt][3],
                             a0, a1, a2, a3, b0, b1);
                }
            }
            __syncthreads();
        }

        // Final normalize; store ctx as fp16 (consumed directly by out GEMM)
        const float inv0 = 1.0f / lsr[mb + quad];
        const float inv1 = 1.0f / lsr[mb + 8 + quad];
        __half* Op = g_ctx + (((size_t)b * S_ + q0) * E_ + (size_t)h * D_);
        const size_t r0 = (size_t)(mb + quad) * E_;
        const size_t r1 = (size_t)(mb + 8 + quad) * E_;
#pragma unroll
        for (int nt = 0; nt < 16; nt++) {
            const int col = nt * 8 + 2 * tq;
            __half2 v0 = __floats2half2_rn(oc[nt][0] * inv0, oc[nt][1] * inv0);
            __half2 v1 = __floats2half2_rn(oc[nt][2] * inv1, oc[nt][3] * inv1);
            *(uint32_t*)(Op + r0 + col) = *(uint32_t*)&v0;
            *(uint32_t*)(Op + r1 + col) = *(uint32_t*)&v1;
        }
    }
}

// ---------------------------------------------------------------------------
// Launch
// ---------------------------------------------------------------------------
extern "C" void kernel_launch(void* const* d_in, const int* in_sizes, int n_in,
                              void* d_out, int out_size)
{
    const float* x  = (const float*)d_in[0];
    const float* Wq = (const float*)d_in[1];
    const float* Wk = (const float*)d_in[2];
    const float* Wv = (const float*)d_in[3];
    const float* Wo = (const float*)d_in[4];
    const float* bo = (const float*)d_in[5];
    float* out = (float*)d_out;

    (void)in_sizes; (void)n_in; (void)out_size;

    // Pre-pass: x -> fp16; weights -> transposed fp16 [n][k]
    cvt_x_kernel<<<512, 256>>>(x);
    transpose_w_kernel<<<dim3(E_ / 32, E_ / 32, 4), dim3(32, 8)>>>(Wq, Wk, Wv, Wo);

    // smem attributes (>48KB dynamic)
    cudaFuncSetAttribute(qkv_kernel,
                         cudaFuncAttributeMaxDynamicSharedMemorySize,
                         GEMM_SMEM_BYTES);
    cudaFuncSetAttribute(out_kernel,
                         cudaFuncAttributeMaxDynamicSharedMemorySize,
                         GEMM_SMEM_BYTES);
    cudaFuncSetAttribute(attn_kernel,
                         cudaFuncAttributeMaxDynamicSharedMemorySize,
                         ATT_SMEM_BYTES);

    // Fused QKV projections (fp16 mma; outputs tf32-rounded)
    qkv_kernel<<<dim3(E_ / 128, M_ / 128, 3), 256, GEMM_SMEM_BYTES>>>();

    // Transpose V for coalesced float4 loads in attention
    transpose_v_kernel<<<dim3(S_ / 32, D_ / 32, B_ * H_), dim3(32, 8)>>>();

    // Flash attention (tf32 mma, paired q-tiles, synchronous loads)
    attn_kernel<<<dim3(S_ / 128, H_, B_), 128, ATT_SMEM_BYTES>>>();

    // Output projection + bias (fp16 mma)
    out_kernel<<<dim3(E_ / 128, M_ / 128, 1), 256, GEMM_SMEM_BYTES>>>(bo, out);
}

// round 17
// speedup vs baseline: 1.6631x; 1.0675x over previous
#include <cuda_runtime.h>
#include <cuda_fp16.h>
#include <cfloat>
#include <cmath>
#include <cstdint>

// Problem constants
constexpr int B_ = 2;
constexpr int S_ = 2048;
constexpr int E_ = 2048;
constexpr int H_ = 16;
constexpr int D_ = 128;
constexpr int M_ = B_ * S_;   // 4096 rows for all GEMMs

// Scratch (static device globals: allowed; no dynamic allocation)
__device__ float g_Q[(size_t)B_ * S_ * E_];
__device__ float g_K[(size_t)B_ * S_ * E_];
__device__ float g_V[(size_t)B_ * S_ * E_];
__device__ float g_VT[(size_t)B_ * H_ * D_ * S_];               // V transposed [bh][d][s]
__device__ __align__(256) __half g_ctx[(size_t)B_ * S_ * E_];   // fp16 ctx
// prepared GEMM inputs (fp16): x row-major [m][k]; weights transposed [n][k]
__device__ __align__(256) __half g_Xh [(size_t)M_ * E_];
__device__ __align__(256) __half g_WqT[(size_t)E_ * E_];
__device__ __align__(256) __half g_WkT[(size_t)E_ * E_];
__device__ __align__(256) __half g_WvT[(size_t)E_ * E_];
__device__ __align__(256) __half g_WoT[(size_t)E_ * E_];

// ---------------------------------------------------------------------------
// helpers
// ---------------------------------------------------------------------------
__device__ __forceinline__ uint32_t f2tf32(float x) {
    uint32_t u;
    asm("cvt.rna.tf32.f32 %0, %1;" : "=r"(u) : "f"(x));
    return u;
}
__device__ __forceinline__ float f2tf32f(float x) {
    return __uint_as_float(f2tf32(x));
}

__device__ __forceinline__ void cp_async16(uint32_t dst, const void* src) {
    asm volatile("cp.async.cg.shared.global [%0], [%1], 16;\n"
                 :: "r"(dst), "l"(src));
}
__device__ __forceinline__ void cp_commit() {
    asm volatile("cp.async.commit_group;\n");
}
template <int N>
__device__ __forceinline__ void cp_wait() {
    asm volatile("cp.async.wait_group %0;\n" :: "n"(N));
}

// fp16 MMA, fp32 accumulate: D(16x8) += A(16x16) * B(16x8)
__device__ __forceinline__ void mma_fp16(
    float* c, uint32_t a0, uint32_t a1, uint32_t a2, uint32_t a3,
    uint32_t b0, uint32_t b1)
{
    asm volatile(
        "mma.sync.aligned.m16n8k16.row.col.f32.f16.f16.f32 "
        "{%0,%1,%2,%3}, {%4,%5,%6,%7}, {%8,%9}, {%0,%1,%2,%3};\n"
        : "+f"(c[0]), "+f"(c[1]), "+f"(c[2]), "+f"(c[3])
        : "r"(a0), "r"(a1), "r"(a2), "r"(a3), "r"(b0), "r"(b1));
}

// tf32 MMA (attention)
__device__ __forceinline__ void mma_tf32(
    float& c0, float& c1, float& c2, float& c3,
    uint32_t a0, uint32_t a1, uint32_t a2, uint32_t a3,
    uint32_t b0, uint32_t b1)
{
    asm volatile(
        "mma.sync.aligned.m16n8k8.row.col.f32.tf32.tf32.f32 "
        "{%0,%1,%2,%3}, {%4,%5,%6,%7}, {%8,%9}, {%0,%1,%2,%3};\n"
        : "+f"(c0), "+f"(c1), "+f"(c2), "+f"(c3)
        : "r"(a0), "r"(a1), "r"(a2), "r"(a3), "r"(b0), "r"(b1));
}

// ---------------------------------------------------------------------------
// Pre-pass: x -> fp16; weights -> transposed [n][k] fp16
// ---------------------------------------------------------------------------
__global__ void __launch_bounds__(256) cvt_x_kernel(const float* __restrict__ x)
{
    const size_t n4 = (size_t)M_ * E_ / 4;
    const size_t stride = (size_t)gridDim.x * blockDim.x;
    for (size_t i = (size_t)blockIdx.x * blockDim.x + threadIdx.x; i < n4;
         i += stride) {
        float4 v = ((const float4*)x)[i];
        __half2 h0 = __floats2half2_rn(v.x, v.y);
        __half2 h1 = __floats2half2_rn(v.z, v.w);
        uint2 o;
        o.x = *(uint32_t*)&h0;
        o.y = *(uint32_t*)&h1;
        ((uint2*)g_Xh)[i] = o;
    }
}

__global__ void __launch_bounds__(256) transpose_w_kernel(
    const float* __restrict__ wq, const float* __restrict__ wk,
    const float* __restrict__ wv, const float* __restrict__ wo)
{
    const float* src; __half* dst;
    switch (blockIdx.z) {
        case 0: src = wq; dst = g_WqT; break;
        case 1: src = wk; dst = g_WkT; break;
        case 2: src = wv; dst = g_WvT; break;
        default: src = wo; dst = g_WoT; break;
    }
    __shared__ float t[32][33];
    const int tx = threadIdx.x, ty = threadIdx.y;
    const int bx = blockIdx.x * 32, by = blockIdx.y * 32;
#pragma unroll
    for (int i = 0; i < 4; i++)
        t[ty + i * 8][tx] = src[(size_t)(by + ty + i * 8) * E_ + bx + tx];
    __syncthreads();
#pragma unroll
    for (int i = 0; i < 4; i++)
        dst[(size_t)(bx + ty + i * 8) * E_ + by + tx] =
            __float2half_rn(t[tx][ty + i * 8]);
}

// Transpose V (after qkv): g_VT[bh][d][s] = g_V[b][s][h*128+d] (already tf32)
__global__ void __launch_bounds__(256) transpose_v_kernel()
{
    const int bh = blockIdx.z;            // b*16+h
    const int b  = bh >> 4;
    const int h  = bh & 15;
    __shared__ float t[32][33];
    const int tx = threadIdx.x, ty = threadIdx.y;
    const int s0 = blockIdx.x * 32, d0 = blockIdx.y * 32;
#pragma unroll
    for (int i = 0; i < 4; i++)
        t[ty + i * 8][tx] =
            g_V[((size_t)(b * S_ + s0 + ty + i * 8)) * E_ + h * D_ + d0 + tx];
    __syncthreads();
#pragma unroll
    for (int i = 0; i < 4; i++)
        g_VT[((size_t)bh * D_ + d0 + ty + i * 8) * S_ + s0 + tx] =
            t[tx][ty + i * 8];
}

// ---------------------------------------------------------------------------
// fp16 tensor-core GEMM: C[M,N] = A[M,K] @ Wt^T  (Wt is [N,K] fp16 K-major)
// CTA tile 128x128, 8 warps, warp tile 64x32. BK=32, 3-stage cp.async.
// ROUND: round outputs to tf32 (Q/K/V feeding the tf32 attention).
// ---------------------------------------------------------------------------
constexpr int NT_K      = E_ / 32;
constexpr int AROW_H    = 40;
constexpr int A_STAGE_B = 128 * AROW_H * 2;        // 10240
constexpr int B_STAGE_B = 128 * AROW_H * 2;        // 10240
constexpr int STAGE_B   = A_STAGE_B + B_STAGE_B;   // 20480
constexpr int NSTG      = 3;
constexpr int GEMM_SMEM_BYTES = NSTG * STAGE_B;    // 61440

template <bool ROUND>
__device__ __forceinline__ void gemm_fp16_128x128(
    const __half* __restrict__ A, const __half* __restrict__ Wt,
    float* __restrict__ C, const float* __restrict__ bias)
{
    constexpr int K = E_;
    constexpr int N = E_;
    extern __shared__ char sm8[];
    const uint32_t sb = (uint32_t)__cvta_generic_to_shared(sm8);

    const int tid  = threadIdx.x;
    const int lane = tid & 31;
    const int warp = tid >> 5;
    const int quad = lane >> 2;
    const int tq   = lane & 3;
    const int wm   = warp >> 2;
    const int wn   = warp & 3;
    const int bm0  = blockIdx.y * 128;
    const int bn0  = blockIdx.x * 128;

    float acc[4][4][4];
#pragma unroll
    for (int mt = 0; mt < 4; mt++)
#pragma unroll
        for (int nt = 0; nt < 4; nt++)
#pragma unroll
            for (int r = 0; r < 4; r++) acc[mt][nt][r] = 0.f;

    auto load_tile = [&](int t) {
        const uint32_t so = sb + (uint32_t)((t % NSTG) * STAGE_B);
        const __half* Ag = A  + (size_t)bm0 * K + t * 32;
        const __half* Bg = Wt + (size_t)bn0 * K + t * 32;
#pragma unroll
        for (int i = 0; i < 2; i++) {
            int idx = tid + i * 256;
            int r = idx >> 2, c = idx & 3;
            cp_async16(so + r * 80 + c * 16, Ag + (size_t)r * K + c * 8);
        }
#pragma unroll
        for (int i = 0; i < 2; i++) {
            int idx = tid + i * 256;
            int r = idx >> 2, c = idx & 3;
            cp_async16(so + A_STAGE_B + r * 80 + c * 16,
                       Bg + (size_t)r * K + c * 8);
        }
        cp_commit();
    };

    load_tile(0);
    load_tile(1);

    for (int t = 0; t < NT_K; t++) {
        if (t + 1 < NT_K) cp_wait<1>(); else cp_wait<0>();
        __syncthreads();
        if (t + 2 < NT_K) load_tile(t + 2);

        const uint32_t* Ah =
            (const uint32_t*)(sm8 + (t % NSTG) * STAGE_B);
        const uint32_t* Bh =
            (const uint32_t*)(sm8 + (t % NSTG) * STAGE_B + A_STAGE_B);

#pragma unroll
        for (int kc = 0; kc < 2; kc++) {
            const int k0 = kc * 8;
            uint32_t a[4][4], b[4][2];
#pragma unroll
            for (int mt = 0; mt < 4; mt++) {
                const int mb = wm * 64 + mt * 16;
                a[mt][0] = Ah[(mb + quad)     * 20 + k0 + tq];
                a[mt][1] = Ah[(mb + 8 + quad) * 20 + k0 + tq];
                a[mt][2] = Ah[(mb + quad)     * 20 + k0 + 4 + tq];
                a[mt][3] = Ah[(mb + 8 + quad) * 20 + k0 + 4 + tq];
            }
#pragma unroll
            for (int nt = 0; nt < 4; nt++) {
                const int nb = wn * 32 + nt * 8;
                b[nt][0] = Bh[(nb + quad) * 20 + k0 + tq];
                b[nt][1] = Bh[(nb + quad) * 20 + k0 + 4 + tq];
            }
#pragma unroll
            for (int mt = 0; mt < 4; mt++)
#pragma unroll
                for (int nt = 0; nt < 4; nt++)
                    mma_fp16(acc[mt][nt],
                             a[mt][0], a[mt][1], a[mt][2], a[mt][3],
                             b[nt][0], b[nt][1]);
        }
    }

    // Epilogue
#pragma unroll
    for (int mt = 0; mt < 4; mt++) {
        const int row = bm0 + wm * 64 + mt * 16 + quad;
#pragma unroll
        for (int nt = 0; nt < 4; nt++) {
            const int col = bn0 + wn * 32 + nt * 8 + 2 * tq;
            float bv0 = bias ? bias[col]     : 0.f;
            float bv1 = bias ? bias[col + 1] : 0.f;
            float2 r0, r1;
            r0.x = acc[mt][nt][0] + bv0; r0.y = acc[mt][nt][1] + bv1;
            r1.x = acc[mt][nt][2] + bv0; r1.y = acc[mt][nt][3] + bv1;
            if (ROUND) {
                r0.x = f2tf32f(r0.x); r0.y = f2tf32f(r0.y);
                r1.x = f2tf32f(r1.x); r1.y = f2tf32f(r1.y);
            }
            *(float2*)(C + (size_t)row * N + col)       = r0;
            *(float2*)(C + (size_t)(row + 8) * N + col) = r1;
        }
    }
}

__global__ void __launch_bounds__(256, 2) qkv_kernel()
{
    const __half* Wt = (blockIdx.z == 0) ? g_WqT
                     : (blockIdx.z == 1) ? g_WkT : g_WvT;
    float* C = (blockIdx.z == 0) ? g_Q : (blockIdx.z == 1) ? g_K : g_V;
    gemm_fp16_128x128<true>(g_Xh, Wt, C, nullptr);   // tf32-rounded outputs
}

__global__ void __launch_bounds__(256, 2) out_kernel(
    const float* __restrict__ bo, float* __restrict__ out)
{
    gemm_fp16_128x128<false>(g_ctx, g_WoT, out, bo);
}

// ---------------------------------------------------------------------------
// Flash attention, tf32 mma, cp.async-pipelined (R15 design, issue_K FIXED:
// 16 chunks/thread covering the full 64x128 K tile).
// CTA = 128 thr (4 warps x 16 q-rows), q-tile pair (qt, 31-qt) = 33 k-tiles.
// Q fragments in registers (staged once per q-tile via K buffer).
// V(t) copy overlaps Phase A+softmax; K(t+1) copy overlaps softmax+Phase B.
// ---------------------------------------------------------------------------
constexpr int KB_ST = 132;   // K buffer stride (floats)
constexpr int VT_ST = 68;    // Vt / Ssm stride (floats)

constexpr int OFF_K   = 0;                      // [64][132] = 8448
constexpr int OFF_VT  = OFF_K + 64 * KB_ST;     // [128][68] = 8704
constexpr int OFF_S   = OFF_VT + 128 * VT_ST;   // [64][68]  = 4352
constexpr int OFF_M   = OFF_S + 64 * VT_ST;
constexpr int OFF_L   = OFF_M + 64;
constexpr int OFF_C   = OFF_L + 64;
constexpr int ATT_SMEM_FLOATS = OFF_C + 64;     // 21696
constexpr int ATT_SMEM_BYTES  = ATT_SMEM_FLOATS * 4;  // 86784

__global__ void __launch_bounds__(128, 2) attn_kernel()
{
    const int tid  = threadIdx.x;
    const int lane = tid & 31;
    const int warp = tid >> 5;
    const int quad = lane >> 2;
    const int tq   = lane & 3;
    const int mb   = warp * 16;

    const int h  = blockIdx.y;
    const int b  = blockIdx.z;
    const int bh = b * H_ + h;
    constexpr int NQT = S_ / 64;                 // 32

    extern __shared__ float sm[];
    float* Kb  = sm + OFF_K;
    float* Vt  = sm + OFF_VT;
    float* Ssm = sm + OFF_S;
    float* msr = sm + OFF_M;
    float* lsr = sm + OFF_L;
    float* csr = sm + OFF_C;
    const uint32_t sbK = (uint32_t)__cvta_generic_to_shared(Kb);
    const uint32_t sbV = (uint32_t)__cvta_generic_to_shared(Vt);

    const float slope = exp2f(-0.5f * (float)(h + 1));
    const float inv_s = rsqrtf((float)D_);

    // async loaders (FULL tile coverage: 2048 16B chunks each)
    auto issue_K = [&](int kt) {   // K tile [64 rows][128 floats] -> Kb
        const float* Kg = g_K + (((size_t)b * S_ + kt * 64) * E_ + (size_t)h * D_);
#pragma unroll
        for (int i = 0; i < 16; i++) {
            int idx = tid + i * 128;          // 0..2047
            int r = idx >> 5, c = idx & 31;   // r 0..63, c*4 0..124
            cp_async16(sbK + (uint32_t)(r * KB_ST + c * 4) * 4,
                       Kg + (size_t)r * E_ + c * 4);
        }
        cp_commit();
    };
    auto issue_V = [&](int kt) {   // Vt tile [128 d][64 j] -> Vt
        const float* Vg = g_VT + ((size_t)bh * D_) * S_ + kt * 64;
#pragma unroll
        for (int i = 0; i < 16; i++) {
            int idx = tid + i * 128;          // 0..2047
            int d = idx >> 4, c = idx & 15;   // d 0..127, c*4 0..60
            cp_async16(sbV + (uint32_t)(d * VT_ST + c * 4) * 4,
                       Vg + (size_t)d * S_ + c * 4);
        }
        cp_commit();
    };

    for (int pi = 0; pi < 2; pi++) {
        const int qt = pi ? (NQT - 1 - (int)blockIdx.x) : (int)blockIdx.x;
        const int q0 = qt * 64;
        const int NT = qt + 1;

        __syncthreads();   // previous q-tile fully done

        // --- Stage Q into Kb (plain float4 copies; data already tf32) ---
        {
            const float* Qp =
                g_Q + (((size_t)b * S_ + q0) * E_ + (size_t)h * D_);
#pragma unroll
            for (int it = 0; it < 16; it++) {
                int idx = tid + it * 128;
                int r   = idx >> 5;
                int c4  = (idx & 31) << 2;
                *(float4*)&Kb[r * KB_ST + c4] =
                    *(const float4*)(Qp + (size_t)r * E_ + c4);
            }
            if (tid < 64) { msr[tid] = -FLT_MAX; lsr[tid] = 0.f; }
        }
        __syncthreads();

        // Extract Q fragments to registers
        uint32_t qa[64];
#pragma unroll
        for (int ks = 0; ks < 16; ks++) {
            const int k0 = ks * 8;
            qa[ks * 4 + 0] = __float_as_uint(Kb[(mb + quad)     * KB_ST + k0 + tq]);
            qa[ks * 4 + 1] = __float_as_uint(Kb[(mb + 8 + quad) * KB_ST + k0 + tq]);
            qa[ks * 4 + 2] = __float_as_uint(Kb[(mb + quad)     * KB_ST + k0 + 4 + tq]);
            qa[ks * 4 + 3] = __float_as_uint(Kb[(mb + 8 + quad) * KB_ST + k0 + 4 + tq]);
        }

        float oc[16][4];
#pragma unroll
        for (int nt = 0; nt < 16; nt++)
#pragma unroll
            for (int r = 0; r < 4; r++) oc[nt][r] = 0.f;

        __syncthreads();   // qa extracted; Kb free
        issue_K(0);

        for (int t = 0; t < NT; t++) {
            const int k0g = t * 64;

            cp_wait<0>();        // K(t) landed
            __syncthreads();     // visible to all; Vt free (prev Phase B done)
            issue_V(t);          // overlaps Phase A + softmax

            // --- Phase A: S(16x64 per warp) = Q @ K^T ---
            float sc[8][4];
#pragma unroll
            for (int nt = 0; nt < 8; nt++)
#pragma unroll
                for (int r = 0; r < 4; r++) sc[nt][r] = 0.f;

#pragma unroll
            for (int ks = 0; ks < 16; ks++) {
                const int k0 = ks * 8;
                uint32_t bb[8][2];
#pragma unroll
                for (int nt = 0; nt < 8; nt++) {
                    const int nb = nt * 8;
                    bb[nt][0] = __float_as_uint(Kb[(nb + quad) * KB_ST + k0 + tq]);
                    bb[nt][1] = __float_as_uint(Kb[(nb + quad) * KB_ST + k0 + 4 + tq]);
                }
#pragma unroll
                for (int nt = 0; nt < 8; nt++)
                    mma_tf32(sc[nt][0], sc[nt][1], sc[nt][2], sc[nt][3],
                             qa[ks * 4], qa[ks * 4 + 1],
                             qa[ks * 4 + 2], qa[ks * 4 + 3],
                             bb[nt][0], bb[nt][1]);
            }

            // mask -> +alibi -> scale (reference order)
            const int ig0 = q0 + mb + quad;
            const int ig1 = ig0 + 8;
#pragma unroll
            for (int nt = 0; nt < 8; nt++) {
                const int col = nt * 8 + 2 * tq;
                const int jg0 = k0g + col;
#pragma unroll
                for (int e = 0; e < 2; e++) {
                    const int jg = jg0 + e;
                    float s0 = sc[nt][e];
                    float s1 = sc[nt][2 + e];
                    if (jg > ig0) s0 = -1e30f;
                    if (jg > ig1) s1 = -1e30f;
                    s0 = (s0 + slope * (float)(jg - ig0)) * inv_s;
                    s1 = (s1 + slope * (float)(jg - ig1)) * inv_s;
                    Ssm[(mb + quad)     * VT_ST + col + e] = s0;
                    Ssm[(mb + 8 + quad) * VT_ST + col + e] = s1;
                }
            }
            __syncthreads();                  // all Phase-A Kb reads done
            if (t + 1 < NT) issue_K(t + 1);   // overlaps softmax + Phase B

            // --- Online softmax: 2 threads per row (own warp's rows) ---
            {
                const int r = tid >> 1, p = tid & 1;
                float* row = Ssm + r * VT_ST + p * 32;
                float lm = -FLT_MAX;
#pragma unroll 8
                for (int j2 = 0; j2 < 32; j2++) lm = fmaxf(lm, row[j2]);
                lm = fmaxf(lm, __shfl_xor_sync(0xffffffffu, lm, 1));
                const float mo = msr[r];
                const float mn = fmaxf(mo, lm);
                const float cc = __expf(mo - mn);
                float s = 0.f;
#pragma unroll 8
                for (int j2 = 0; j2 < 32; j2++) {
                    float pv = __expf(row[j2] - mn);
                    pv = f2tf32f(pv);
                    row[j2] = pv;
                    s += pv;
                }
                s += __shfl_xor_sync(0xffffffffu, s, 1);
                if (!p) {
                    msr[r] = mn;
                    lsr[r] = cc * lsr[r] + s;
                    csr[r] = cc;
                }
            }

            if (t + 1 < NT) cp_wait<1>();   // V(t) landed; K(t+1) in flight
            else            cp_wait<0>();   // drain
            __syncthreads();                // V visible; stats published

            // --- Phase B: O = c*O + P @ V ---
            const float cr0 = csr[mb + quad];
            const float cr1 = csr[mb + 8 + quad];
#pragma unroll
            for (int nt = 0; nt < 16; nt++) {
                oc[nt][0] *= cr0; oc[nt][1] *= cr0;
                oc[nt][2] *= cr1; oc[nt][3] *= cr1;
            }

#pragma unroll
            for (int kk = 0; kk < 8; kk++) {
                const int k0 = kk * 8;
                uint32_t a0 = __float_as_uint(Ssm[(mb + quad)     * VT_ST + k0 + tq]);
                uint32_t a1 = __float_as_uint(Ssm[(mb + 8 + quad) * VT_ST + k0 + tq]);
                uint32_t a2 = __float_as_uint(Ssm[(mb + quad)     * VT_ST + k0 + 4 + tq]);
                uint32_t a3 = __float_as_uint(Ssm[(mb + 8 + quad) * VT_ST + k0 + 4 + tq]);
#pragma unroll
                for (int nt = 0; nt < 16; nt++) {
                    const int nb = nt * 8;
                    uint32_t b0 = __float_as_uint(Vt[(nb + quad) * VT_ST + k0 + tq]);
                    uint32_t b1 = __float_as_uint(Vt[(nb + quad) * VT_ST + k0 + 4 + tq]);
                    mma_tf32(oc[nt][0], oc[nt][1], oc[nt][2], oc[nt][3],
                             a0, a1, a2, a3, b0, b1);
                }
            }
        }

        // Final normalize; store ctx as fp16 (consumed directly by out GEMM)
        const float inv0 = 1.0f / lsr[mb + quad];
        const float inv1 = 1.0f / lsr[mb + 8 + quad];
        __half* Op = g_ctx + (((size_t)b * S_ + q0) * E_ + (size_t)h * D_);
        const size_t r0 = (size_t)(mb + quad) * E_;
        const size_t r1 = (size_t)(mb + 8 + quad) * E_;
#pragma unroll
        for (int nt = 0; nt < 16; nt++) {
            const int col = nt * 8 + 2 * tq;
            __half2 v0 = __floats2half2_rn(oc[nt][0] * inv0, oc[nt][1] * inv0);
            __half2 v1 = __floats2half2_rn(oc[nt][2] * inv1, oc[nt][3] * inv1);
            *(uint32_t*)(Op + r0 + col) = *(uint32_t*)&v0;
            *(uint32_t*)(Op + r1 + col) = *(uint32_t*)&v1;
        }
    }
}

// ---------------------------------------------------------------------------
// Launch
// ---------------------------------------------------------------------------
extern "C" void kernel_launch(void* const* d_in, const int* in_sizes, int n_in,
                              void* d_out, int out_size)
{
    const float* x  = (const float*)d_in[0];
    const float* Wq = (const float*)d_in[1];
    const float* Wk = (const float*)d_in[2];
    const float* Wv = (const float*)d_in[3];
    const float* Wo = (const float*)d_in[4];
    const float* bo = (const float*)d_in[5];
    float* out = (float*)d_out;

    (void)in_sizes; (void)n_in; (void)out_size;

    // Pre-pass: x -> fp16; weights -> transposed fp16 [n][k]
    cvt_x_kernel<<<512, 256>>>(x);
    transpose_w_kernel<<<dim3(E_ / 32, E_ / 32, 4), dim3(32, 8)>>>(Wq, Wk, Wv, Wo);

    // smem attributes (>48KB dynamic)
    cudaFuncSetAttribute(qkv_kernel,
                         cudaFuncAttributeMaxDynamicSharedMemorySize,
                         GEMM_SMEM_BYTES);
    cudaFuncSetAttribute(out_kernel,
                         cudaFuncAttributeMaxDynamicSharedMemorySize,
                         GEMM_SMEM_BYTES);
    cudaFuncSetAttribute(attn_kernel,
                         cudaFuncAttributeMaxDynamicSharedMemorySize,
                         ATT_SMEM_BYTES);

    // Fused QKV projections (fp16 mma; outputs tf32-rounded)
    qkv_kernel<<<dim3(E_ / 128, M_ / 128, 3), 256, GEMM_SMEM_BYTES>>>();

    // Transpose V for coalesced float4/cp.async loads in attention
    transpose_v_kernel<<<dim3(S_ / 32, D_ / 32, B_ * H_), dim3(32, 8)>>>();

    // Flash attention (tf32 mma, cp.async pipelined, paired q-tiles)
    attn_kernel<<<dim3(S_ / 128, H_, B_), 128, ATT_SMEM_BYTES>>>();

    // Output projection + bias (fp16 mma)
    out_kernel<<<dim3(E_ / 128, M_ / 128, 1), 256, GEMM_SMEM_BYTES>>>(bo, out);
}